// round 5
// baseline (speedup 1.0000x reference)
#include <cuda_runtime.h>
#include <math.h>
#include <stdint.h>

// ---------------- problem constants ----------------
#define NN      20000      // nodes
#define FEAT    128
#define E0      100000     // undirected edges
#define EDG     200000     // directed (doubled)
#define NRBF    20
#define NCONV   3
#define CUTOFF  20.0f
#define PI_F    3.14159265358979323846f

#define NF      (NN*FEAT)          // 2,560,000
#define N3F     (NN*384)           // 7,680,000

// ---------------- device scratch (no cudaMalloc allowed) ----------------
__device__ float g_sA[NF];
__device__ float g_sB[NF];
__device__ float g_vA[3*NF];
__device__ float g_vB[3*NF];
__device__ float g_phi[N3F];
__device__ float g_hid[NF];
__device__ float g_uv[3*NF];
__device__ float g_vv[3*NF];
__device__ float g_xcat[NN*256];
__device__ float g_am[N3F];
__device__ float g_unit[EDG*3];
__device__ float g_rbf[EDG*NRBF];
__device__ float g_env[EDG];
__device__ int   g_ei[EDG];
__device__ int   g_ej[EDG];

// ---------------- helpers ----------------
__device__ __forceinline__ float tf32_rna(float x) {
    uint32_t u; asm("cvt.rna.tf32.f32 %0, %1;" : "=r"(u) : "f"(x));
    return __uint_as_float(u);
}
__device__ __forceinline__ void mma_tf32(float* c, const uint32_t* a, uint32_t b0, uint32_t b1) {
    asm volatile(
        "mma.sync.aligned.m16n8k8.row.col.f32.tf32.tf32.f32 "
        "{%0,%1,%2,%3}, {%4,%5,%6,%7}, {%8,%9}, {%0,%1,%2,%3};"
        : "+f"(c[0]), "+f"(c[1]), "+f"(c[2]), "+f"(c[3])
        : "r"(a[0]), "r"(a[1]), "r"(a[2]), "r"(a[3]), "r"(b0), "r"(b1));
}

// ---------------- small utility kernels ----------------
__global__ void copy4_kernel(float4* __restrict__ dst, const float4* __restrict__ src, int n4) {
    int i = blockIdx.x * blockDim.x + threadIdx.x;
    if (i < n4) dst[i] = src[i];
}
__global__ void zero4_kernel(float4* __restrict__ dst, int n4) {
    int i = blockIdx.x * blockDim.x + threadIdx.x;
    if (i < n4) dst[i] = make_float4(0.f,0.f,0.f,0.f);
}

// ---------------- edge geometry precompute ----------------
__global__ void edge_geom_kernel(const float* __restrict__ xyz, const int* __restrict__ nbr,
                                 float* __restrict__ unit, float* __restrict__ rbf,
                                 float* __restrict__ env, int* __restrict__ ei, int* __restrict__ ej) {
    int e = blockIdx.x * blockDim.x + threadIdx.x;
    if (e >= EDG) return;
    int p = (e < E0) ? e : (e - E0);
    int a = nbr[p*2], b = nbr[p*2+1];
    int i = (e < E0) ? a : b;
    int j = (e < E0) ? b : a;
    float dx = xyz[j*3+0] - xyz[i*3+0];
    float dy = xyz[j*3+1] - xyz[i*3+1];
    float dz = xyz[j*3+2] - xyz[i*3+2];
    float d  = sqrtf(dx*dx + dy*dy + dz*dz);
    float invd = 1.0f / d;
    unit[e*3+0] = dx*invd; unit[e*3+1] = dy*invd; unit[e*3+2] = dz*invd;
    #pragma unroll
    for (int k = 0; k < NRBF; k++)
        rbf[e*NRBF + k] = sinf((float)(k+1) * PI_F * d / CUTOFF) * invd;
    env[e] = (d < CUTOFF) ? 0.5f * (cosf(PI_F * d / CUTOFF) + 1.0f) : 0.0f;
    ei[e] = i; ej[e] = j;
}

// =====================================================================
// mma.sync TF32x3 GEMM:  C = act(A @ W^T + b)
// CTA tile 64x128, 128 threads (4 warps, 2x2), warp tile 32x64.
// K chunks of 16, single-buffered; occupancy target 4 CTAs/SM.
// Optional fused twin GEMM (W2/C2) sharing A, selected by blockIdx.x.
// =====================================================================
#define PITCH 20
template<bool SILU>
__global__ void __launch_bounds__(128, 4)
mma_gemm_kernel(const float* __restrict__ A, size_t aStride,
                const float* __restrict__ W, const float* __restrict__ W2,
                const float* __restrict__ bias,
                float* __restrict__ C, float* __restrict__ C2, size_t cStride,
                int Nrows, int Mcols, int K) {
    __shared__ float Ah[64][PITCH];
    __shared__ float Al[64][PITCH];
    __shared__ float Bh[128][PITCH];
    __shared__ float Bl[128][PITCH];

    const int tid = threadIdx.x;
    const int wid = tid >> 5;
    const int lid = tid & 31;
    const int tq  = lid >> 2;     // 0..7
    const int tr  = lid & 3;      // 0..3
    const int warpRow = (wid & 1) * 32;
    const int warpCol = (wid >> 1) * 64;
    const int rowBase = blockIdx.y * 64;

    // select W/C pair (fused twin GEMM support)
    const int colTiles = (Mcols + 127) >> 7;
    int bx = blockIdx.x;
    const float* Wsel = W;
    float* Csel = C;
    if (W2 != nullptr && bx >= colTiles) { Wsel = W2; Csel = C2; bx -= colTiles; }
    const int colBase = bx * 128;

    A    += (size_t)blockIdx.z * aStride;
    Csel += (size_t)blockIdx.z * cStride;
    const float* Wt = Wsel + (size_t)colBase * K;

    float acc[2][8][4];
    #pragma unroll
    for (int mf = 0; mf < 2; mf++)
        #pragma unroll
        for (int nf = 0; nf < 8; nf++)
            #pragma unroll
            for (int u = 0; u < 4; u++) acc[mf][nf][u] = 0.f;

    const int rowA = tid >> 1;          // 0..63
    const int qA   = (tid & 1) * 8;     // 0 or 8

    for (int k0 = 0; k0 < K; k0 += 16) {
        // ---- stage A: 64x16, 2 float4 per thread ----
        {
            int r = rowBase + rowA;
            const float* src = &A[(size_t)r * K + k0 + qA];
            float4 a0 = (r < Nrows) ? *(const float4*)(src)     : make_float4(0.f,0.f,0.f,0.f);
            float4 a1 = (r < Nrows) ? *(const float4*)(src + 4) : make_float4(0.f,0.f,0.f,0.f);
            float4 h, l;
            h.x = tf32_rna(a0.x); l.x = a0.x - h.x;
            h.y = tf32_rna(a0.y); l.y = a0.y - h.y;
            h.z = tf32_rna(a0.z); l.z = a0.z - h.z;
            h.w = tf32_rna(a0.w); l.w = a0.w - h.w;
            *(float4*)&Ah[rowA][qA] = h;
            *(float4*)&Al[rowA][qA] = l;
            h.x = tf32_rna(a1.x); l.x = a1.x - h.x;
            h.y = tf32_rna(a1.y); l.y = a1.y - h.y;
            h.z = tf32_rna(a1.z); l.z = a1.z - h.z;
            h.w = tf32_rna(a1.w); l.w = a1.w - h.w;
            *(float4*)&Ah[rowA][qA + 4] = h;
            *(float4*)&Al[rowA][qA + 4] = l;
        }
        // ---- stage B: 128x16, 4 float4 per thread (row = tid) ----
        {
            const float* src = &Wt[(size_t)tid * K + k0];
            #pragma unroll
            for (int q = 0; q < 4; q++) {
                float4 bv = *(const float4*)(src + q * 4);
                float4 h, l;
                h.x = tf32_rna(bv.x); l.x = bv.x - h.x;
                h.y = tf32_rna(bv.y); l.y = bv.y - h.y;
                h.z = tf32_rna(bv.z); l.z = bv.z - h.z;
                h.w = tf32_rna(bv.w); l.w = bv.w - h.w;
                *(float4*)&Bh[tid][q * 4] = h;
                *(float4*)&Bl[tid][q * 4] = l;
            }
        }
        __syncthreads();

        // ---- compute: 2 k-steps of 8 ----
        #pragma unroll
        for (int ks = 0; ks < 2; ks++) {
            const int kc = ks * 8;
            uint32_t ah[2][4], al[2][4];
            #pragma unroll
            for (int mf = 0; mf < 2; mf++) {
                int r0 = warpRow + mf * 16 + tq;
                ah[mf][0] = __float_as_uint(Ah[r0    ][kc + tr    ]);
                ah[mf][1] = __float_as_uint(Ah[r0 + 8][kc + tr    ]);
                ah[mf][2] = __float_as_uint(Ah[r0    ][kc + tr + 4]);
                ah[mf][3] = __float_as_uint(Ah[r0 + 8][kc + tr + 4]);
                al[mf][0] = __float_as_uint(Al[r0    ][kc + tr    ]);
                al[mf][1] = __float_as_uint(Al[r0 + 8][kc + tr    ]);
                al[mf][2] = __float_as_uint(Al[r0    ][kc + tr + 4]);
                al[mf][3] = __float_as_uint(Al[r0 + 8][kc + tr + 4]);
            }
            #pragma unroll
            for (int nf = 0; nf < 8; nf++) {
                int c0 = warpCol + nf * 8 + tq;
                uint32_t bh0 = __float_as_uint(Bh[c0][kc + tr    ]);
                uint32_t bh1 = __float_as_uint(Bh[c0][kc + tr + 4]);
                uint32_t bl0 = __float_as_uint(Bl[c0][kc + tr    ]);
                uint32_t bl1 = __float_as_uint(Bl[c0][kc + tr + 4]);
                #pragma unroll
                for (int mf = 0; mf < 2; mf++) {
                    mma_tf32(acc[mf][nf], ah[mf], bh0, bh1);
                    mma_tf32(acc[mf][nf], al[mf], bh0, bh1);
                    mma_tf32(acc[mf][nf], ah[mf], bl0, bl1);
                }
            }
        }
        __syncthreads();
    }

    // ---- epilogue: bias + activation + direct float2 stores ----
    #pragma unroll
    for (int mf = 0; mf < 2; mf++) {
        int r0 = rowBase + warpRow + mf * 16 + tq;
        #pragma unroll
        for (int nf = 0; nf < 8; nf++) {
            int cb = colBase + warpCol + nf * 8 + tr * 2;
            float b0 = bias ? bias[cb] : 0.f;
            float b1 = bias ? bias[cb + 1] : 0.f;
            float v0 = acc[mf][nf][0] + b0;
            float v1 = acc[mf][nf][1] + b1;
            float v2 = acc[mf][nf][2] + b0;
            float v3 = acc[mf][nf][3] + b1;
            if (SILU) {
                v0 = v0 / (1.f + expf(-v0));
                v1 = v1 / (1.f + expf(-v1));
                v2 = v2 / (1.f + expf(-v2));
                v3 = v3 / (1.f + expf(-v3));
            }
            if (r0 < Nrows)      *(float2*)&Csel[(size_t)r0      * Mcols + cb] = make_float2(v0, v1);
            if (r0 + 8 < Nrows)  *(float2*)&Csel[(size_t)(r0 + 8) * Mcols + cb] = make_float2(v2, v3);
        }
    }
}

// ---------------- edge message: w_s, inv, scatter-add ----------------
__global__ void edge_msg_kernel(const float* __restrict__ phi,
                                const float* __restrict__ v_old,
                                const float* __restrict__ distW,
                                const float* __restrict__ distb,
                                const int* __restrict__ ei, const int* __restrict__ ej,
                                const float* __restrict__ unit, const float* __restrict__ rbf,
                                const float* __restrict__ env,
                                float* __restrict__ s_acc, float* __restrict__ v_acc) {
    __shared__ float dw[384*21];
    __shared__ float db[384];
    const int tid = threadIdx.x;
    for (int idx = tid; idx < 384*NRBF; idx += 256)
        dw[(idx/NRBF)*21 + (idx%NRBF)] = distW[idx];
    for (int idx = tid; idx < 384; idx += 256) db[idx] = distb[idx];
    __syncthreads();

    const int slot = tid >> 7;   // 0 or 1
    const int f    = tid & 127;
    for (int e = blockIdx.x*2 + slot; e < EDG; e += gridDim.x*2) {
        int i = ei[e], j = ej[e];
        float rb[NRBF];
        #pragma unroll
        for (int k = 0; k < NRBF; k++) rb[k] = rbf[e*NRBF + k];
        float ev = env[e];
        float u0 = unit[e*3+0], u1 = unit[e*3+1], u2 = unit[e*3+2];
        float inv[3];
        #pragma unroll
        for (int c = 0; c < 3; c++) {
            int ch = c*128 + f;
            const float* w = &dw[ch*21];
            float acc = db[ch];
            #pragma unroll
            for (int k = 0; k < NRBF; k++) acc += rb[k] * w[k];
            inv[c] = phi[(size_t)j*384 + ch] * (acc * ev);
        }
        atomicAdd(&s_acc[(size_t)i*128 + f], inv[1]);
        #pragma unroll
        for (int d = 0; d < 3; d++) {
            float vj = v_old[(size_t)d*NF + (size_t)j*128 + f];
            float ud = (d == 0) ? u0 : ((d == 1) ? u1 : u2);
            float dv = inv[2]*ud + inv[0]*vj;
            atomicAdd(&v_acc[(size_t)d*NF + (size_t)i*128 + f], dv);
        }
    }
}

// ---------------- xcat = [s, ||v_v||] ----------------
__global__ void xcat_kernel(const float* __restrict__ s, const float* __restrict__ vv,
                            float* __restrict__ xcat) {
    int idx = blockIdx.x * blockDim.x + threadIdx.x;
    if (idx >= NF) return;
    int n = idx >> 7, f = idx & 127;
    float a = vv[idx], b = vv[NF + idx], c = vv[2*NF + idx];
    xcat[(size_t)n*256 + f]       = s[idx];
    xcat[(size_t)n*256 + 128 + f] = sqrtf(a*a + b*b + c*c);
}

// ---------------- final gated update (in place) ----------------
__global__ void update_kernel(const float* __restrict__ uv, const float* __restrict__ vv,
                              const float* __restrict__ am,
                              float* __restrict__ s, float* __restrict__ v) {
    int idx = blockIdx.x * blockDim.x + threadIdx.x;
    if (idx >= NF) return;
    int n = idx >> 7, f = idx & 127;
    float dot = uv[idx]*vv[idx] + uv[NF+idx]*vv[NF+idx] + uv[2*NF+idx]*vv[2*NF+idx];
    float a0 = am[(size_t)n*384 + f];
    float a1 = am[(size_t)n*384 + 128 + f];
    float a2 = am[(size_t)n*384 + 256 + f];
    s[idx] += dot * a1 + a2;
    #pragma unroll
    for (int d = 0; d < 3; d++)
        v[(size_t)d*NF + idx] += uv[(size_t)d*NF + idx] * a0;
}

// ---------------- pack output: s flat, then v as (N,128,3) ----------------
__global__ void output_kernel(const float* __restrict__ s, const float* __restrict__ v,
                              float* __restrict__ out) {
    int idx = blockIdx.x * blockDim.x + threadIdx.x;
    if (idx >= NF) return;
    int n = idx >> 7, f = idx & 127;
    out[idx] = s[idx];
    #pragma unroll
    for (int d = 0; d < 3; d++)
        out[(size_t)NF + (size_t)n*384 + f*3 + d] = v[(size_t)d*NF + idx];
}

// ---------------- host orchestration ----------------
extern "C" void kernel_launch(void* const* d_in, const int* in_sizes, int n_in,
                              void* d_out, int out_size) {
    const float* xyz    = (const float*)d_in[0];
    const int*   nbr    = (const int*)  d_in[1];
    const float* cg_s   = (const float*)d_in[2];
    const float* msg_W1 = (const float*)d_in[3];
    const float* msg_b1 = (const float*)d_in[4];
    const float* msg_W2 = (const float*)d_in[5];
    const float* msg_b2 = (const float*)d_in[6];
    const float* dist_W = (const float*)d_in[7];
    const float* dist_b = (const float*)d_in[8];
    const float* upd_U  = (const float*)d_in[9];
    const float* upd_V  = (const float*)d_in[10];
    const float* upd_sW1= (const float*)d_in[11];
    const float* upd_sb1= (const float*)d_in[12];
    const float* upd_sW2= (const float*)d_in[13];
    const float* upd_sb2= (const float*)d_in[14];
    float* out = (float*)d_out;

    float *sA, *sB, *vA, *vB, *phi, *hid, *uv, *vv, *xcat, *am, *unit, *rbf, *env;
    int *ei, *ej;
    cudaGetSymbolAddress((void**)&sA,   g_sA);
    cudaGetSymbolAddress((void**)&sB,   g_sB);
    cudaGetSymbolAddress((void**)&vA,   g_vA);
    cudaGetSymbolAddress((void**)&vB,   g_vB);
    cudaGetSymbolAddress((void**)&phi,  g_phi);
    cudaGetSymbolAddress((void**)&hid,  g_hid);
    cudaGetSymbolAddress((void**)&uv,   g_uv);
    cudaGetSymbolAddress((void**)&vv,   g_vv);
    cudaGetSymbolAddress((void**)&xcat, g_xcat);
    cudaGetSymbolAddress((void**)&am,   g_am);
    cudaGetSymbolAddress((void**)&unit, g_unit);
    cudaGetSymbolAddress((void**)&rbf,  g_rbf);
    cudaGetSymbolAddress((void**)&env,  g_env);
    cudaGetSymbolAddress((void**)&ei,   g_ei);
    cudaGetSymbolAddress((void**)&ej,   g_ej);

    const int TPB = 256;
    copy4_kernel<<<(NF/4 + TPB-1)/TPB, TPB>>>((float4*)sA, (const float4*)cg_s, NF/4);
    zero4_kernel<<<(3*NF/4 + TPB-1)/TPB, TPB>>>((float4*)vA, 3*NF/4);
    edge_geom_kernel<<<(EDG + TPB-1)/TPB, TPB>>>(xyz, nbr, unit, rbf, env, ei, ej);

    const int RT = (NN + 63) / 64;   // 313 row tiles
    float* s_cur = sA; float* s_nxt = sB;
    float* v_cur = vA; float* v_nxt = vB;

    for (int l = 0; l < NCONV; l++) {
        // phi = silu(s @ W1^T + b1) @ W2^T + b2
        mma_gemm_kernel<true ><<<dim3(1, RT, 1), 128>>>(
            s_cur, 0, msg_W1 + (size_t)l*FEAT*FEAT, nullptr, msg_b1 + (size_t)l*FEAT,
            hid, nullptr, 0, NN, FEAT, FEAT);
        mma_gemm_kernel<false><<<dim3(3, RT, 1), 128>>>(
            hid, 0, msg_W2 + (size_t)l*384*FEAT, nullptr, msg_b2 + (size_t)l*384,
            phi, nullptr, 0, NN, 384, FEAT);
        // accumulators = current state
        copy4_kernel<<<(NF/4 + TPB-1)/TPB, TPB>>>((float4*)s_nxt, (const float4*)s_cur, NF/4);
        copy4_kernel<<<(3*NF/4 + TPB-1)/TPB, TPB>>>((float4*)v_nxt, (const float4*)v_cur, 3*NF/4);
        // edge messages + scatter
        edge_msg_kernel<<<1184, TPB>>>(phi, v_cur,
                                       dist_W + (size_t)l*384*NRBF, dist_b + (size_t)l*384,
                                       ei, ej, unit, rbf, env, s_nxt, v_nxt);
        // u_v and v_v fused (shared A tile), batched over 3 spatial dims
        mma_gemm_kernel<false><<<dim3(2, RT, 3), 128>>>(
            v_nxt, (size_t)NF, upd_U + (size_t)l*FEAT*FEAT, upd_V + (size_t)l*FEAT*FEAT,
            nullptr, uv, vv, (size_t)NF, NN, FEAT, FEAT);
        // xcat = [s, ||v_v||]
        xcat_kernel<<<(NF + TPB-1)/TPB, TPB>>>(s_nxt, vv, xcat);
        // a = silu(xcat @ sW1^T + sb1) @ sW2^T + sb2
        mma_gemm_kernel<true ><<<dim3(1, RT, 1), 128>>>(
            xcat, 0, upd_sW1 + (size_t)l*FEAT*256, nullptr, upd_sb1 + (size_t)l*FEAT,
            hid, nullptr, 0, NN, FEAT, 256);
        mma_gemm_kernel<false><<<dim3(3, RT, 1), 128>>>(
            hid, 0, upd_sW2 + (size_t)l*384*FEAT, nullptr, upd_sb2 + (size_t)l*384,
            am, nullptr, 0, NN, 384, FEAT);
        // gated update
        update_kernel<<<(NF + TPB-1)/TPB, TPB>>>(uv, vv, am, s_nxt, v_nxt);

        float* t;
        t = s_cur; s_cur = s_nxt; s_nxt = t;
        t = v_cur; v_cur = v_nxt; v_nxt = t;
    }

    output_kernel<<<(NF + TPB-1)/TPB, TPB>>>(s_cur, v_cur, out);
}

// round 6
// speedup vs baseline: 1.6548x; 1.6548x over previous
#include <cuda_runtime.h>
#include <math.h>
#include <stdint.h>

// ---------------- problem constants ----------------
#define NN      20000      // nodes
#define FEAT    128
#define E0      100000     // undirected edges
#define EDG     200000     // directed (doubled)
#define NRBF    20
#define NCONV   3
#define CUTOFF  20.0f
#define PI_F    3.14159265358979323846f

#define NF      (NN*FEAT)          // 2,560,000
#define N3F     (NN*384)           // 7,680,000

// ---------------- device scratch (no cudaMalloc allowed) ----------------
__device__ float g_s [NF];
__device__ float g_vA[3*NF];
__device__ float g_vB[3*NF];
__device__ float g_phi[N3F];
__device__ float g_hid[NF];
__device__ float g_uv[3*NF];
__device__ float g_vv[3*NF];
__device__ float g_xcat[NN*256];
__device__ float g_am[N3F];
__device__ float g_unit[EDG*3];
__device__ float g_rbf[EDG*NRBF];
__device__ float g_env[EDG];
__device__ int   g_ei[EDG];
__device__ int   g_ej[EDG];

// ---------------- helpers ----------------
__device__ __forceinline__ float tf32_rna(float x) {
    uint32_t u; asm("cvt.rna.tf32.f32 %0, %1;" : "=r"(u) : "f"(x));
    return __uint_as_float(u);
}
__device__ __forceinline__ void mma_tf32(float* c, const uint32_t* a, uint32_t b0, uint32_t b1) {
    asm volatile(
        "mma.sync.aligned.m16n8k8.row.col.f32.tf32.tf32.f32 "
        "{%0,%1,%2,%3}, {%4,%5,%6,%7}, {%8,%9}, {%0,%1,%2,%3};"
        : "+f"(c[0]), "+f"(c[1]), "+f"(c[2]), "+f"(c[3])
        : "r"(a[0]), "r"(a[1]), "r"(a[2]), "r"(a[3]), "r"(b0), "r"(b1));
}
__device__ __forceinline__ void cp16(uint32_t dst, const void* src, bool pred) {
    int sz = pred ? 16 : 0;
    asm volatile("cp.async.ca.shared.global [%0], [%1], 16, %2;"
                 :: "r"(dst), "l"(src), "r"(sz) : "memory");
}

// ---------------- small utility kernels ----------------
__global__ void copy4_kernel(float4* __restrict__ dst, const float4* __restrict__ src, int n4) {
    int i = blockIdx.x * blockDim.x + threadIdx.x;
    if (i < n4) dst[i] = src[i];
}
__global__ void zero4_kernel(float4* __restrict__ dst, int n4) {
    int i = blockIdx.x * blockDim.x + threadIdx.x;
    if (i < n4) dst[i] = make_float4(0.f,0.f,0.f,0.f);
}

// ---------------- edge geometry precompute ----------------
__global__ void edge_geom_kernel(const float* __restrict__ xyz, const int* __restrict__ nbr,
                                 float* __restrict__ unit, float* __restrict__ rbf,
                                 float* __restrict__ env, int* __restrict__ ei, int* __restrict__ ej) {
    int e = blockIdx.x * blockDim.x + threadIdx.x;
    if (e >= EDG) return;
    int p = (e < E0) ? e : (e - E0);
    int a = nbr[p*2], b = nbr[p*2+1];
    int i = (e < E0) ? a : b;
    int j = (e < E0) ? b : a;
    float dx = xyz[j*3+0] - xyz[i*3+0];
    float dy = xyz[j*3+1] - xyz[i*3+1];
    float dz = xyz[j*3+2] - xyz[i*3+2];
    float d  = sqrtf(dx*dx + dy*dy + dz*dz);
    float invd = 1.0f / d;
    unit[e*3+0] = dx*invd; unit[e*3+1] = dy*invd; unit[e*3+2] = dz*invd;
    #pragma unroll
    for (int k = 0; k < NRBF; k++)
        rbf[e*NRBF + k] = sinf((float)(k+1) * PI_F * d / CUTOFF) * invd;
    env[e] = (d < CUTOFF) ? 0.5f * (cosf(PI_F * d / CUTOFF) + 1.0f) : 0.0f;
    ei[e] = i; ej[e] = j;
}

// =====================================================================
// mma.sync TF32x3 GEMM, cp.async 2-stage pipeline, reg-side hi/lo split.
// C = act(A @ W^T + b). CTA tile 128x128, 256 threads (8 warps 4x2),
// warp tile 32x64 (proven R3 frag layout). Raw fp32 staged in smem;
// tf32 hi/lo computed in registers after frag load (halves LDS + smem).
// Optional fused twin GEMM (W2/C2) sharing A, selected by blockIdx.x.
// =====================================================================
#define PITCH 20
template<bool SILU>
__global__ void __launch_bounds__(256)
mma_gemm_kernel(const float* __restrict__ A, size_t aStride,
                const float* __restrict__ W, const float* __restrict__ W2,
                const float* __restrict__ bias,
                float* __restrict__ C, float* __restrict__ C2, size_t cStride,
                int Nrows, int Mcols, int K) {
    __shared__ float As[2][128 * PITCH];
    __shared__ float Bs[2][128 * PITCH];

    const int tid = threadIdx.x;
    const int wid = tid >> 5;
    const int lid = tid & 31;
    const int tq  = lid >> 2;     // 0..7
    const int tr  = lid & 3;      // 0..3
    const int warpRow = (wid & 3) * 32;
    const int warpCol = (wid >> 2) * 64;
    const int rowBase = blockIdx.y * 128;

    // select W/C pair (fused twin GEMM support)
    const int colTiles = (Mcols + 127) >> 7;
    int bx = blockIdx.x;
    const float* Wsel = W;
    float* Csel = C;
    if (W2 != nullptr && bx >= colTiles) { Wsel = W2; Csel = C2; bx -= colTiles; }
    const int colBase = bx * 128;

    A    += (size_t)blockIdx.z * aStride;
    Csel += (size_t)blockIdx.z * cStride;
    const float* Wt = Wsel + (size_t)colBase * K;

    const uint32_t aSm0 = (uint32_t)__cvta_generic_to_shared(&As[0][0]);
    const uint32_t aSm1 = (uint32_t)__cvta_generic_to_shared(&As[1][0]);
    const uint32_t bSm0 = (uint32_t)__cvta_generic_to_shared(&Bs[0][0]);
    const uint32_t bSm1 = (uint32_t)__cvta_generic_to_shared(&Bs[1][0]);

    const int ldRow0 = tid >> 2;        // 0..63
    const int ldQ    = (tid & 3) * 4;   // 0,4,8,12

    float acc[2][8][4];
    #pragma unroll
    for (int mf = 0; mf < 2; mf++)
        #pragma unroll
        for (int nf = 0; nf < 8; nf++)
            #pragma unroll
            for (int u = 0; u < 4; u++) acc[mf][nf][u] = 0.f;

    const int nch = K >> 4;

    // issue cp.async for chunk c into buffer buf
    auto issue_stage = [&](int c, int buf) {
        const int k0 = c * 16;
        uint32_t aSm = buf ? aSm1 : aSm0;
        uint32_t bSm = buf ? bSm1 : bSm0;
        #pragma unroll
        for (int half = 0; half < 2; half++) {
            int row = half * 64 + ldRow0;
            int r = rowBase + row;
            uint32_t soff = (uint32_t)(row * PITCH + ldQ) * 4u;
            cp16(aSm + soff, &A[(size_t)r * K + k0 + ldQ], r < Nrows);
            cp16(bSm + soff, &Wt[(size_t)row * K + k0 + ldQ], true);
        }
        asm volatile("cp.async.commit_group;" ::: "memory");
    };

    issue_stage(0, 0);

    for (int c = 0; c < nch; c++) {
        if (c + 1 < nch) {
            issue_stage(c + 1, (c + 1) & 1);
            asm volatile("cp.async.wait_group 1;" ::: "memory");
        } else {
            asm volatile("cp.async.wait_group 0;" ::: "memory");
        }
        __syncthreads();

        const float* Ab = As[c & 1];
        const float* Bb = Bs[c & 1];

        #pragma unroll
        for (int ks = 0; ks < 2; ks++) {
            const int kc = ks * 8;
            uint32_t ah[2][4], al[2][4];
            #pragma unroll
            for (int mf = 0; mf < 2; mf++) {
                int r0 = warpRow + mf * 16 + tq;
                float a0 = Ab[(r0    ) * PITCH + kc + tr    ];
                float a1 = Ab[(r0 + 8) * PITCH + kc + tr    ];
                float a2 = Ab[(r0    ) * PITCH + kc + tr + 4];
                float a3 = Ab[(r0 + 8) * PITCH + kc + tr + 4];
                float h0 = tf32_rna(a0), h1 = tf32_rna(a1), h2 = tf32_rna(a2), h3 = tf32_rna(a3);
                ah[mf][0] = __float_as_uint(h0); al[mf][0] = __float_as_uint(a0 - h0);
                ah[mf][1] = __float_as_uint(h1); al[mf][1] = __float_as_uint(a1 - h1);
                ah[mf][2] = __float_as_uint(h2); al[mf][2] = __float_as_uint(a2 - h2);
                ah[mf][3] = __float_as_uint(h3); al[mf][3] = __float_as_uint(a3 - h3);
            }
            #pragma unroll
            for (int nf = 0; nf < 8; nf++) {
                int c0 = warpCol + nf * 8 + tq;
                float b0 = Bb[c0 * PITCH + kc + tr    ];
                float b1 = Bb[c0 * PITCH + kc + tr + 4];
                float bh0f = tf32_rna(b0), bh1f = tf32_rna(b1);
                uint32_t bh0 = __float_as_uint(bh0f);
                uint32_t bh1 = __float_as_uint(bh1f);
                uint32_t bl0 = __float_as_uint(b0 - bh0f);
                uint32_t bl1 = __float_as_uint(b1 - bh1f);
                #pragma unroll
                for (int mf = 0; mf < 2; mf++) {
                    mma_tf32(acc[mf][nf], ah[mf], bh0, bh1);
                    mma_tf32(acc[mf][nf], al[mf], bh0, bh1);
                    mma_tf32(acc[mf][nf], ah[mf], bl0, bl1);
                }
            }
        }
        __syncthreads();
    }

    // ---- epilogue: bias + activation + direct float2 stores ----
    #pragma unroll
    for (int mf = 0; mf < 2; mf++) {
        int r0 = rowBase + warpRow + mf * 16 + tq;
        #pragma unroll
        for (int nf = 0; nf < 8; nf++) {
            int cb = colBase + warpCol + nf * 8 + tr * 2;
            float b0 = bias ? bias[cb] : 0.f;
            float b1 = bias ? bias[cb + 1] : 0.f;
            float v0 = acc[mf][nf][0] + b0;
            float v1 = acc[mf][nf][1] + b1;
            float v2 = acc[mf][nf][2] + b0;
            float v3 = acc[mf][nf][3] + b1;
            if (SILU) {
                v0 = v0 / (1.f + expf(-v0));
                v1 = v1 / (1.f + expf(-v1));
                v2 = v2 / (1.f + expf(-v2));
                v3 = v3 / (1.f + expf(-v3));
            }
            if (r0 < Nrows)      *(float2*)&Csel[(size_t)r0      * Mcols + cb] = make_float2(v0, v1);
            if (r0 + 8 < Nrows)  *(float2*)&Csel[(size_t)(r0 + 8) * Mcols + cb] = make_float2(v2, v3);
        }
    }
}

// ---------------- edge message: w_s, inv, scatter-add ----------------
__global__ void edge_msg_kernel(const float* __restrict__ phi,
                                const float* __restrict__ v_old,
                                const float* __restrict__ distW,
                                const float* __restrict__ distb,
                                const int* __restrict__ ei, const int* __restrict__ ej,
                                const float* __restrict__ unit, const float* __restrict__ rbf,
                                const float* __restrict__ env,
                                float* __restrict__ s_acc, float* __restrict__ v_acc) {
    __shared__ float dw[384*21];
    __shared__ float db[384];
    const int tid = threadIdx.x;
    for (int idx = tid; idx < 384*NRBF; idx += 256)
        dw[(idx/NRBF)*21 + (idx%NRBF)] = distW[idx];
    for (int idx = tid; idx < 384; idx += 256) db[idx] = distb[idx];
    __syncthreads();

    const int slot = tid >> 7;   // 0 or 1
    const int f    = tid & 127;
    for (int e = blockIdx.x*2 + slot; e < EDG; e += gridDim.x*2) {
        int i = ei[e], j = ej[e];
        float rb[NRBF];
        #pragma unroll
        for (int k = 0; k < NRBF; k++) rb[k] = rbf[e*NRBF + k];
        float ev = env[e];
        float u0 = unit[e*3+0], u1 = unit[e*3+1], u2 = unit[e*3+2];
        float inv[3];
        #pragma unroll
        for (int c = 0; c < 3; c++) {
            int ch = c*128 + f;
            const float* w = &dw[ch*21];
            float acc = db[ch];
            #pragma unroll
            for (int k = 0; k < NRBF; k++) acc += rb[k] * w[k];
            inv[c] = phi[(size_t)j*384 + ch] * (acc * ev);
        }
        atomicAdd(&s_acc[(size_t)i*128 + f], inv[1]);
        #pragma unroll
        for (int d = 0; d < 3; d++) {
            float vj = v_old[(size_t)d*NF + (size_t)j*128 + f];
            float ud = (d == 0) ? u0 : ((d == 1) ? u1 : u2);
            float dv = inv[2]*ud + inv[0]*vj;
            atomicAdd(&v_acc[(size_t)d*NF + (size_t)i*128 + f], dv);
        }
    }
}

// ---------------- xcat = [s, ||v_v||] ----------------
__global__ void xcat_kernel(const float* __restrict__ s, const float* __restrict__ vv,
                            float* __restrict__ xcat) {
    int idx = blockIdx.x * blockDim.x + threadIdx.x;
    if (idx >= NF) return;
    int n = idx >> 7, f = idx & 127;
    float a = vv[idx], b = vv[NF + idx], c = vv[2*NF + idx];
    xcat[(size_t)n*256 + f]       = s[idx];
    xcat[(size_t)n*256 + 128 + f] = sqrtf(a*a + b*b + c*c);
}

// ---------------- final gated update (in place) ----------------
__global__ void update_kernel(const float* __restrict__ uv, const float* __restrict__ vv,
                              const float* __restrict__ am,
                              float* __restrict__ s, float* __restrict__ v) {
    int idx = blockIdx.x * blockDim.x + threadIdx.x;
    if (idx >= NF) return;
    int n = idx >> 7, f = idx & 127;
    float dot = uv[idx]*vv[idx] + uv[NF+idx]*vv[NF+idx] + uv[2*NF+idx]*vv[2*NF+idx];
    float a0 = am[(size_t)n*384 + f];
    float a1 = am[(size_t)n*384 + 128 + f];
    float a2 = am[(size_t)n*384 + 256 + f];
    s[idx] += dot * a1 + a2;
    #pragma unroll
    for (int d = 0; d < 3; d++)
        v[(size_t)d*NF + idx] += uv[(size_t)d*NF + idx] * a0;
}

// ---------------- pack output: s flat, then v as (N,128,3) ----------------
__global__ void output_kernel(const float* __restrict__ s, const float* __restrict__ v,
                              float* __restrict__ out) {
    int idx = blockIdx.x * blockDim.x + threadIdx.x;
    if (idx >= NF) return;
    int n = idx >> 7, f = idx & 127;
    out[idx] = s[idx];
    #pragma unroll
    for (int d = 0; d < 3; d++)
        out[(size_t)NF + (size_t)n*384 + f*3 + d] = v[(size_t)d*NF + idx];
}

// ---------------- host orchestration ----------------
extern "C" void kernel_launch(void* const* d_in, const int* in_sizes, int n_in,
                              void* d_out, int out_size) {
    const float* xyz    = (const float*)d_in[0];
    const int*   nbr    = (const int*)  d_in[1];
    const float* cg_s   = (const float*)d_in[2];
    const float* msg_W1 = (const float*)d_in[3];
    const float* msg_b1 = (const float*)d_in[4];
    const float* msg_W2 = (const float*)d_in[5];
    const float* msg_b2 = (const float*)d_in[6];
    const float* dist_W = (const float*)d_in[7];
    const float* dist_b = (const float*)d_in[8];
    const float* upd_U  = (const float*)d_in[9];
    const float* upd_V  = (const float*)d_in[10];
    const float* upd_sW1= (const float*)d_in[11];
    const float* upd_sb1= (const float*)d_in[12];
    const float* upd_sW2= (const float*)d_in[13];
    const float* upd_sb2= (const float*)d_in[14];
    float* out = (float*)d_out;

    float *s, *vA, *vB, *phi, *hid, *uv, *vv, *xcat, *am, *unit, *rbf, *env;
    int *ei, *ej;
    cudaGetSymbolAddress((void**)&s,    g_s);
    cudaGetSymbolAddress((void**)&vA,   g_vA);
    cudaGetSymbolAddress((void**)&vB,   g_vB);
    cudaGetSymbolAddress((void**)&phi,  g_phi);
    cudaGetSymbolAddress((void**)&hid,  g_hid);
    cudaGetSymbolAddress((void**)&uv,   g_uv);
    cudaGetSymbolAddress((void**)&vv,   g_vv);
    cudaGetSymbolAddress((void**)&xcat, g_xcat);
    cudaGetSymbolAddress((void**)&am,   g_am);
    cudaGetSymbolAddress((void**)&unit, g_unit);
    cudaGetSymbolAddress((void**)&rbf,  g_rbf);
    cudaGetSymbolAddress((void**)&env,  g_env);
    cudaGetSymbolAddress((void**)&ei,   g_ei);
    cudaGetSymbolAddress((void**)&ej,   g_ej);

    const int TPB = 256;
    copy4_kernel<<<(NF/4 + TPB-1)/TPB, TPB>>>((float4*)s, (const float4*)cg_s, NF/4);
    zero4_kernel<<<(3*NF/4 + TPB-1)/TPB, TPB>>>((float4*)vA, 3*NF/4);
    edge_geom_kernel<<<(EDG + TPB-1)/TPB, TPB>>>(xyz, nbr, unit, rbf, env, ei, ej);

    const int RT = (NN + 127) / 128;   // 157 row tiles
    float* v_cur = vA; float* v_nxt = vB;

    for (int l = 0; l < NCONV; l++) {
        // phi = silu(s @ W1^T + b1) @ W2^T + b2
        mma_gemm_kernel<true ><<<dim3(1, RT, 1), TPB>>>(
            s, 0, msg_W1 + (size_t)l*FEAT*FEAT, nullptr, msg_b1 + (size_t)l*FEAT,
            hid, nullptr, 0, NN, FEAT, FEAT);
        mma_gemm_kernel<false><<<dim3(3, RT, 1), TPB>>>(
            hid, 0, msg_W2 + (size_t)l*384*FEAT, nullptr, msg_b2 + (size_t)l*384,
            phi, nullptr, 0, NN, 384, FEAT);
        // v accumulator = current v (s scatters in place — phi already computed)
        copy4_kernel<<<(3*NF/4 + TPB-1)/TPB, TPB>>>((float4*)v_nxt, (const float4*)v_cur, 3*NF/4);
        // edge messages + scatter (s in place, v into v_nxt reading v_cur)
        edge_msg_kernel<<<1184, TPB>>>(phi, v_cur,
                                       dist_W + (size_t)l*384*NRBF, dist_b + (size_t)l*384,
                                       ei, ej, unit, rbf, env, s, v_nxt);
        // u_v and v_v fused (shared A tile), batched over 3 spatial dims
        mma_gemm_kernel<false><<<dim3(2, RT, 3), TPB>>>(
            v_nxt, (size_t)NF, upd_U + (size_t)l*FEAT*FEAT, upd_V + (size_t)l*FEAT*FEAT,
            nullptr, uv, vv, (size_t)NF, NN, FEAT, FEAT);
        // xcat = [s, ||v_v||]
        xcat_kernel<<<(NF + TPB-1)/TPB, TPB>>>(s, vv, xcat);
        // a = silu(xcat @ sW1^T + sb1) @ sW2^T + sb2
        mma_gemm_kernel<true ><<<dim3(1, RT, 1), TPB>>>(
            xcat, 0, upd_sW1 + (size_t)l*FEAT*256, nullptr, upd_sb1 + (size_t)l*FEAT,
            hid, nullptr, 0, NN, FEAT, 256);
        mma_gemm_kernel<false><<<dim3(3, RT, 1), TPB>>>(
            hid, 0, upd_sW2 + (size_t)l*384*FEAT, nullptr, upd_sb2 + (size_t)l*384,
            am, nullptr, 0, NN, 384, FEAT);
        // gated update (s and v_nxt in place)
        update_kernel<<<(NF + TPB-1)/TPB, TPB>>>(uv, vv, am, s, v_nxt);

        float* t = v_cur; v_cur = v_nxt; v_nxt = t;
    }

    output_kernel<<<(NF + TPB-1)/TPB, TPB>>>(s, v_cur, out);
}